// round 1
// baseline (speedup 1.0000x reference)
#include <cuda_runtime.h>

// ScaledDotProductAttention: B=4, H=8, S=2048, D=64, fp32.
// mask[b,1,q,k] != 0 => position excluded (score -1e9 pre-softmax, attn zeroed post-softmax).
// Flash-attention style: one CTA per (b, h, 64-row q tile), online softmax over 64-wide k tiles.

#define SLEN 2048
#define HD   64
#define TQ   64
#define TK   64

__global__ __launch_bounds__(256, 2)
void fa_fp32_kernel(const float* __restrict__ Qg, const float* __restrict__ Kg,
                    const float* __restrict__ Vg, const int* __restrict__ Mg,
                    float* __restrict__ Og) {
    // Static smem: exactly 48 KB.
    __shared__ float Qt[HD * TQ];   // [d][q]  (Q transposed, prescaled by 1/sqrt(64))
    __shared__ float KtP[HD * TK];  // [d][k] during S-gemm; reused as P[q][k] for PV-gemm
    __shared__ float Vs[TK * HD];   // [k][d]

    const int tid = threadIdx.x;
    const int tx  = tid & 15;       // column group (4 cols)
    const int ty  = tid >> 4;       // row group (4 rows)
    const int qt  = blockIdx.x;
    const int h   = blockIdx.y;
    const int b   = blockIdx.z;
    const int bh  = b * 8 + h;

    const float* Qp = Qg + ((size_t)bh * SLEN + (size_t)qt * TQ) * HD;
    const float* Kp = Kg + (size_t)bh * SLEN * HD;
    const float* Vp = Vg + (size_t)bh * SLEN * HD;
    const int*   Mp = Mg + ((size_t)b * SLEN + (size_t)qt * TQ) * SLEN;
    float*       Op = Og + ((size_t)bh * SLEN + (size_t)qt * TQ) * HD;

    // ---- Load Q tile, transpose to d-major, fold in scale 1/sqrt(D)=0.125 ----
    {
        const int row0 = tid >> 4;   // 0..15
        const int f4   = tid & 15;   // float4 column index
        #pragma unroll
        for (int r = 0; r < 4; r++) {
            int rr = r * 16 + row0;
            float4 v = reinterpret_cast<const float4*>(Qp + rr * HD)[f4];
            Qt[(4*f4+0)*TQ + rr] = v.x * 0.125f;
            Qt[(4*f4+1)*TQ + rr] = v.y * 0.125f;
            Qt[(4*f4+2)*TQ + rr] = v.z * 0.125f;
            Qt[(4*f4+3)*TQ + rr] = v.w * 0.125f;
        }
    }

    float acc[4][4] = {};
    float mrow[4] = {-1e30f, -1e30f, -1e30f, -1e30f};
    float lrow[4] = {};

    for (int kt = 0; kt < SLEN / TK; kt++) {
        __syncthreads();   // previous PV-gemm reads of KtP/Vs complete

        // Prefetch mask fragment for this thread's 4x4 (coalesced int4 loads).
        int4 mm[4];
        #pragma unroll
        for (int i = 0; i < 4; i++)
            mm[i] = *reinterpret_cast<const int4*>(Mp + (4*ty+i)*SLEN + kt*TK + 4*tx);

        // Load K tile (transposed to d-major) and V tile (k-major).
        {
            const int row0 = tid >> 4;
            const int f4   = tid & 15;
            #pragma unroll
            for (int r = 0; r < 4; r++) {
                int rr = r * 16 + row0;
                float4 kv = reinterpret_cast<const float4*>(Kp + (size_t)(kt*TK + rr) * HD)[f4];
                KtP[(4*f4+0)*TK + rr] = kv.x;
                KtP[(4*f4+1)*TK + rr] = kv.y;
                KtP[(4*f4+2)*TK + rr] = kv.z;
                KtP[(4*f4+3)*TK + rr] = kv.w;
                float4 vv = reinterpret_cast<const float4*>(Vp + (size_t)(kt*TK + rr) * HD)[f4];
                reinterpret_cast<float4*>(Vs + rr * HD)[f4] = vv;
            }
        }
        __syncthreads();

        // ---- S = (Q*scale) @ K^T : 4x4 fragment per thread ----
        float s[4][4] = {};
        #pragma unroll 8
        for (int d = 0; d < HD; d++) {
            float a0 = Qt[d*TQ + 4*ty+0];
            float a1 = Qt[d*TQ + 4*ty+1];
            float a2 = Qt[d*TQ + 4*ty+2];
            float a3 = Qt[d*TQ + 4*ty+3];
            float b0 = KtP[d*TK + 4*tx+0];
            float b1 = KtP[d*TK + 4*tx+1];
            float b2 = KtP[d*TK + 4*tx+2];
            float b3 = KtP[d*TK + 4*tx+3];
            s[0][0] += a0*b0; s[0][1] += a0*b1; s[0][2] += a0*b2; s[0][3] += a0*b3;
            s[1][0] += a1*b0; s[1][1] += a1*b1; s[1][2] += a1*b2; s[1][3] += a1*b3;
            s[2][0] += a2*b0; s[2][1] += a2*b1; s[2][2] += a2*b2; s[2][3] += a2*b3;
            s[3][0] += a3*b0; s[3][1] += a3*b1; s[3][2] += a3*b2; s[3][3] += a3*b3;
        }

        // ---- apply mask: mask!=0 => excluded ----
        #pragma unroll
        for (int i = 0; i < 4; i++) {
            if (mm[i].x) s[i][0] = -1e30f;
            if (mm[i].y) s[i][1] = -1e30f;
            if (mm[i].z) s[i][2] = -1e30f;
            if (mm[i].w) s[i][3] = -1e30f;
        }

        // ---- online softmax update (row groups of 16 lanes) ----
        #pragma unroll
        for (int i = 0; i < 4; i++) {
            float mx = fmaxf(fmaxf(s[i][0], s[i][1]), fmaxf(s[i][2], s[i][3]));
            #pragma unroll
            for (int w = 1; w < 16; w <<= 1)
                mx = fmaxf(mx, __shfl_xor_sync(0xffffffffu, mx, w));
            float mnew  = fmaxf(mrow[i], mx);
            float alpha = __expf(mrow[i] - mnew);   // both -1e30 -> exp(0)=1, l stays 0
            mrow[i] = mnew;
            float sum = 0.f;
            #pragma unroll
            for (int j = 0; j < 4; j++) {
                float pv = (s[i][j] <= -1e29f) ? 0.f : __expf(s[i][j] - mnew);
                s[i][j] = pv;
                sum += pv;
            }
            #pragma unroll
            for (int w = 1; w < 16; w <<= 1)
                sum += __shfl_xor_sync(0xffffffffu, sum, w);
            lrow[i] = lrow[i] * alpha + sum;
            #pragma unroll
            for (int j = 0; j < 4; j++) acc[i][j] *= alpha;
        }

        __syncthreads();   // all threads done reading Kt before P overwrites it
        #pragma unroll
        for (int i = 0; i < 4; i++)
            #pragma unroll
            for (int j = 0; j < 4; j++)
                KtP[(4*ty+i)*TK + 4*tx+j] = s[i][j];
        __syncthreads();   // P visible to all

        // ---- acc += P @ V ----
        #pragma unroll 8
        for (int k = 0; k < TK; k++) {
            float a0 = KtP[(4*ty+0)*TK + k];
            float a1 = KtP[(4*ty+1)*TK + k];
            float a2 = KtP[(4*ty+2)*TK + k];
            float a3 = KtP[(4*ty+3)*TK + k];
            float b0 = Vs[k*HD + 4*tx+0];
            float b1 = Vs[k*HD + 4*tx+1];
            float b2 = Vs[k*HD + 4*tx+2];
            float b3 = Vs[k*HD + 4*tx+3];
            acc[0][0] += a0*b0; acc[0][1] += a0*b1; acc[0][2] += a0*b2; acc[0][3] += a0*b3;
            acc[1][0] += a1*b0; acc[1][1] += a1*b1; acc[1][2] += a1*b2; acc[1][3] += a1*b3;
            acc[2][0] += a2*b0; acc[2][1] += a2*b1; acc[2][2] += a2*b2; acc[2][3] += a2*b3;
            acc[3][0] += a3*b0; acc[3][1] += a3*b1; acc[3][2] += a3*b2; acc[3][3] += a3*b3;
        }
    }

    // ---- normalize and store (fully-masked row: l==0, acc==0 -> output 0) ----
    #pragma unroll
    for (int i = 0; i < 4; i++) {
        float inv = (lrow[i] > 0.f) ? (1.f / lrow[i]) : 0.f;
        float4 o;
        o.x = acc[i][0] * inv;
        o.y = acc[i][1] * inv;
        o.z = acc[i][2] * inv;
        o.w = acc[i][3] * inv;
        reinterpret_cast<float4*>(Op + (4*ty+i)*HD)[tx] = o;
    }
}

extern "C" void kernel_launch(void* const* d_in, const int* in_sizes, int n_in,
                              void* d_out, int out_size) {
    const float* Q    = (const float*)d_in[0];
    const float* K    = (const float*)d_in[1];
    const float* V    = (const float*)d_in[2];
    const int*   mask = (const int*)d_in[3];
    float* O = (float*)d_out;

    dim3 grid(SLEN / TQ, 8, 4);   // (q-tiles, H, B) = (32, 8, 4)
    dim3 block(256);
    fa_fp32_kernel<<<grid, block>>>(Q, K, V, mask, O);
}

// round 3
// speedup vs baseline: 3.2894x; 3.2894x over previous
#include <cuda_runtime.h>
#include <cuda_fp16.h>
#include <cstdint>

#define SLEN 2048
#define NH   8
#define HD   64
#define TQ   128
#define TK   64
#define NKT  (SLEN / TK)
#define NWORDS (SLEN / 32)

// 2 MB packed mask scratch: bit=1 => position excluded
__device__ uint32_t g_maskbits[4u * SLEN * NWORDS];

__global__ void pack_mask_kernel(const int* __restrict__ Mg) {
    int warp = (blockIdx.x * 256 + threadIdx.x) >> 5;   // 0..8191 = b*2048+q
    int lane = threadIdx.x & 31;
    const int* rp = Mg + (size_t)warp * SLEN;
    uint32_t* wp = g_maskbits + (size_t)warp * NWORDS;
    #pragma unroll 4
    for (int j = 0; j < NWORDS; j++) {
        uint32_t bits = __ballot_sync(0xffffffffu, rp[j * 32 + lane] != 0);
        if (lane == 0) wp[j] = bits;
    }
}

__device__ __forceinline__ uint32_t s2u(const void* p) {
    uint32_t r;
    asm("{ .reg .u64 t; cvta.to.shared.u64 t, %1; cvt.u32.u64 %0, t; }" : "=r"(r) : "l"(p));
    return r;
}
__device__ __forceinline__ void ldsm4(uint32_t& r0, uint32_t& r1, uint32_t& r2, uint32_t& r3,
                                      uint32_t addr) {
    asm volatile("ldmatrix.sync.aligned.m8n8.x4.shared.b16 {%0,%1,%2,%3}, [%4];"
                 : "=r"(r0), "=r"(r1), "=r"(r2), "=r"(r3) : "r"(addr));
}
__device__ __forceinline__ void mma16816(float c[4], uint32_t a0, uint32_t a1, uint32_t a2,
                                         uint32_t a3, uint32_t b0, uint32_t b1) {
    asm volatile(
        "mma.sync.aligned.m16n8k16.row.col.f32.f16.f16.f32 "
        "{%0,%1,%2,%3}, {%4,%5,%6,%7}, {%8,%9}, {%0,%1,%2,%3};"
        : "+f"(c[0]), "+f"(c[1]), "+f"(c[2]), "+f"(c[3])
        : "r"(a0), "r"(a1), "r"(a2), "r"(a3), "r"(b0), "r"(b1));
}
__device__ __forceinline__ uint32_t f2h2(float a, float b) {
    __half2 t = __floats2half2_rn(a, b);
    return *reinterpret_cast<uint32_t*>(&t);
}

// smem byte offsets
#define OQH 0
#define OQL 16384
#define OKH 32768
#define OKL 40960
#define OVT 49152
#define SMEM_TOTAL 57344

__global__ __launch_bounds__(256, 1)
void fa_hmma_kernel(const float* __restrict__ Qg, const float* __restrict__ Kg,
                    const float* __restrict__ Vg, float* __restrict__ Og) {
    extern __shared__ char smem[];
    char* QHp = smem + OQH;  char* QLp = smem + OQL;
    char* KHp = smem + OKH;  char* KLp = smem + OKL;
    char* VTp = smem + OVT;
    const uint32_t QHu = s2u(QHp), QLu = s2u(QLp);
    const uint32_t KHu = s2u(KHp), KLu = s2u(KLp), VTu = s2u(VTp);

    const int tid = threadIdx.x, wid = tid >> 5, lane = tid & 31;
    const int qt = blockIdx.x, h = blockIdx.y, b = blockIdx.z;
    const int bh = b * NH + h;

    const float* Qp = Qg + ((size_t)bh * SLEN + (size_t)qt * TQ) * HD;
    const float* Kp = Kg + (size_t)bh * SLEN * HD;
    const float* Vp = Vg + (size_t)bh * SLEN * HD;

    // ---- Q: load, scale by 1/8, fp16 hi/lo split into swizzled smem ----
    #pragma unroll
    for (int j = 0; j < 8; j++) {
        int linear = tid + j * 256;
        int r = linear >> 4, f4 = linear & 15;
        float4 v = reinterpret_cast<const float4*>(Qp + (size_t)r * HD)[f4];
        v.x *= 0.125f; v.y *= 0.125f; v.z *= 0.125f; v.w *= 0.125f;
        __half hx = __float2half_rn(v.x), hy = __float2half_rn(v.y);
        __half hz = __float2half_rn(v.z), hw = __float2half_rn(v.w);
        __half lx = __float2half_rn(v.x - __half2float(hx));
        __half ly = __float2half_rn(v.y - __half2float(hy));
        __half lz = __float2half_rn(v.z - __half2float(hz));
        __half lw = __float2half_rn(v.w - __half2float(hw));
        int byte = r * 128 + ((((f4 >> 1) ^ (r & 7))) << 4) + (f4 & 1) * 8;
        *(__half2*)(QHp + byte)     = __halves2half2(hx, hy);
        *(__half2*)(QHp + byte + 4) = __halves2half2(hz, hw);
        *(__half2*)(QLp + byte)     = __halves2half2(lx, ly);
        *(__half2*)(QLp + byte + 4) = __halves2half2(lz, lw);
    }
    __syncthreads();

    // ---- preload Q A-fragments (loop invariant) ----
    const int m0 = wid * 16;
    uint32_t qh[4][4], ql[4][4];
    {
        int r = m0 + (lane & 15);
        int rx = r & 7;
        uint32_t rowb = (uint32_t)r * 128u;
        #pragma unroll
        for (int ks = 0; ks < 4; ks++) {
            uint32_t chunk = (uint32_t)(ks * 2 + (lane >> 4));
            uint32_t off = rowb + ((chunk ^ (uint32_t)rx) << 4);
            ldsm4(qh[ks][0], qh[ks][1], qh[ks][2], qh[ks][3], QHu + off);
            ldsm4(ql[ks][0], ql[ks][1], ql[ks][2], ql[ks][3], QLu + off);
        }
    }

    // B-fragment lane constants (ldmatrix.x4 over two n8 tiles)
    const int rb = (lane & 7) + ((lane & 16) >> 1);  // 0..15 row-in-pair
    const int cb = (lane & 8) >> 3;                  // chunk parity

    // mask row pointers for this thread's two rows
    const int r0g = qt * TQ + m0 + (lane >> 2);
    const uint32_t* mb0 = g_maskbits + ((size_t)b * SLEN + r0g) * NWORDS;
    const uint32_t* mb1 = mb0 + 8 * NWORDS;

    float oacc[8][4];
    #pragma unroll
    for (int i = 0; i < 8; i++)
        #pragma unroll
        for (int j = 0; j < 4; j++) oacc[i][j] = 0.f;
    float mold0 = -1e30f, mold1 = -1e30f, lsum0 = 0.f, lsum1 = 0.f;

    // K/V prefetch registers
    float4 kreg[4], vreg[4];
    const int lr = tid >> 2;        // 0..63 row
    {
        const float4* K4 = reinterpret_cast<const float4*>(Kp);
        const float4* V4 = reinterpret_cast<const float4*>(Vp);
        #pragma unroll
        for (int j = 0; j < 4; j++) {
            int f4 = (tid & 3) + j * 4;
            kreg[j] = K4[lr * 16 + f4];
            vreg[j] = V4[lr * 16 + f4];
        }
    }

    for (int kt = 0; kt < NKT; kt++) {
        __syncthreads();   // previous tile fully consumed

        // ---- store K (hi/lo split) + V (fp16, transposed) tiles ----
        {
            int rx = lr & 7;
            #pragma unroll
            for (int j = 0; j < 4; j++) {
                int f4 = (tid & 3) + j * 4;
                float4 kv = kreg[j];
                __half hx = __float2half_rn(kv.x), hy = __float2half_rn(kv.y);
                __half hz = __float2half_rn(kv.z), hw = __float2half_rn(kv.w);
                __half lx = __float2half_rn(kv.x - __half2float(hx));
                __half ly = __float2half_rn(kv.y - __half2float(hy));
                __half lz = __float2half_rn(kv.z - __half2float(hz));
                __half lw = __float2half_rn(kv.w - __half2float(hw));
                int byte = lr * 128 + ((((f4 >> 1) ^ rx)) << 4) + (f4 & 1) * 8;
                *(__half2*)(KHp + byte)     = __halves2half2(hx, hy);
                *(__half2*)(KHp + byte + 4) = __halves2half2(hz, hw);
                *(__half2*)(KLp + byte)     = __halves2half2(lx, ly);
                *(__half2*)(KLp + byte + 4) = __halves2half2(lz, lw);
                float vv[4] = {vreg[j].x, vreg[j].y, vreg[j].z, vreg[j].w};
                #pragma unroll
                for (int e = 0; e < 4; e++) {
                    int d = f4 * 4 + e;
                    int vb = d * 128 + ((((lr >> 3) ^ (d & 7))) << 4) + (lr & 7) * 2;
                    *(__half*)(VTp + vb) = __float2half_rn(vv[e]);
                }
            }
        }
        __syncthreads();

        // prefetch next tile
        if (kt + 1 < NKT) {
            const float4* K4 = reinterpret_cast<const float4*>(Kp + (size_t)(kt + 1) * TK * HD);
            const float4* V4 = reinterpret_cast<const float4*>(Vp + (size_t)(kt + 1) * TK * HD);
            #pragma unroll
            for (int j = 0; j < 4; j++) {
                int f4 = (tid & 3) + j * 4;
                kreg[j] = K4[lr * 16 + f4];
                vreg[j] = V4[lr * 16 + f4];
            }
        }

        uint32_t mw00 = mb0[kt * 2], mw01 = mb0[kt * 2 + 1];
        uint32_t mw10 = mb1[kt * 2], mw11 = mb1[kt * 2 + 1];

        // ---- S = QhKh + QlKh + QhKl ----
        float sacc[8][4];
        #pragma unroll
        for (int i = 0; i < 8; i++)
            #pragma unroll
            for (int j = 0; j < 4; j++) sacc[i][j] = 0.f;

        #pragma unroll
        for (int ntp = 0; ntp < 4; ntp++) {
            #pragma unroll
            for (int ks = 0; ks < 4; ks++) {
                int row = ntp * 16 + rb;
                uint32_t off = (uint32_t)row * 128u +
                               (((uint32_t)(ks * 2 + cb) ^ (uint32_t)(row & 7)) << 4);
                uint32_t h0, h1, h2, h3, l0, l1, l2, l3;
                ldsm4(h0, h1, h2, h3, KHu + off);
                ldsm4(l0, l1, l2, l3, KLu + off);
                mma16816(sacc[2 * ntp],     qh[ks][0], qh[ks][1], qh[ks][2], qh[ks][3], h0, h1);
                mma16816(sacc[2 * ntp + 1], qh[ks][0], qh[ks][1], qh[ks][2], qh[ks][3], h2, h3);
                mma16816(sacc[2 * ntp],     ql[ks][0], ql[ks][1], ql[ks][2], ql[ks][3], h0, h1);
                mma16816(sacc[2 * ntp + 1], ql[ks][0], ql[ks][1], ql[ks][2], ql[ks][3], h2, h3);
                mma16816(sacc[2 * ntp],     qh[ks][0], qh[ks][1], qh[ks][2], qh[ks][3], l0, l1);
                mma16816(sacc[2 * ntp + 1], qh[ks][0], qh[ks][1], qh[ks][2], qh[ks][3], l2, l3);
            }
        }

        // ---- mask ----
        #pragma unroll
        for (int nt = 0; nt < 8; nt++) {
            uint32_t w0 = (nt < 4) ? mw00 : mw01;
            uint32_t w1 = (nt < 4) ? mw10 : mw11;
            int cb2 = (nt * 8 + (lane & 3) * 2) & 31;
            if ((w0 >> cb2) & 1)       sacc[nt][0] = -1e30f;
            if ((w0 >> (cb2 + 1)) & 1) sacc[nt][1] = -1e30f;
            if ((w1 >> cb2) & 1)       sacc[nt][2] = -1e30f;
            if ((w1 >> (cb2 + 1)) & 1) sacc[nt][3] = -1e30f;
        }

        // ---- online softmax (quad reductions; rows r0g, r0g+8) ----
        float mx0 = -1e30f, mx1 = -1e30f;
        #pragma unroll
        for (int nt = 0; nt < 8; nt++) {
            mx0 = fmaxf(mx0, fmaxf(sacc[nt][0], sacc[nt][1]));
            mx1 = fmaxf(mx1, fmaxf(sacc[nt][2], sacc[nt][3]));
        }
        mx0 = fmaxf(mx0, __shfl_xor_sync(0xffffffffu, mx0, 1));
        mx0 = fmaxf(mx0, __shfl_xor_sync(0xffffffffu, mx0, 2));
        mx1 = fmaxf(mx1, __shfl_xor_sync(0xffffffffu, mx1, 1));
        mx1 = fmaxf(mx1, __shfl_xor_sync(0xffffffffu, mx1, 2));
        float mn0 = fmaxf(mold0, mx0), mn1 = fmaxf(mold1, mx1);
        float al0 = __expf(mold0 - mn0), al1 = __expf(mold1 - mn1);
        mold0 = mn0; mold1 = mn1;

        float sum0 = 0.f, sum1 = 0.f;
        #pragma unroll
        for (int nt = 0; nt < 8; nt++) {
            float p0 = (sacc[nt][0] <= -1e29f) ? 0.f : __expf(sacc[nt][0] - mn0);
            float p1 = (sacc[nt][1] <= -1e29f) ? 0.f : __expf(sacc[nt][1] - mn0);
            float p2 = (sacc[nt][2] <= -1e29f) ? 0.f : __expf(sacc[nt][2] - mn1);
            float p3 = (sacc[nt][3] <= -1e29f) ? 0.f : __expf(sacc[nt][3] - mn1);
            sacc[nt][0] = p0; sacc[nt][1] = p1; sacc[nt][2] = p2; sacc[nt][3] = p3;
            sum0 += p0 + p1; sum1 += p2 + p3;
        }
        sum0 += __shfl_xor_sync(0xffffffffu, sum0, 1);
        sum0 += __shfl_xor_sync(0xffffffffu, sum0, 2);
        sum1 += __shfl_xor_sync(0xffffffffu, sum1, 1);
        sum1 += __shfl_xor_sync(0xffffffffu, sum1, 2);
        lsum0 = lsum0 * al0 + sum0;
        lsum1 = lsum1 * al1 + sum1;
        #pragma unroll
        for (int nt = 0; nt < 8; nt++) {
            oacc[nt][0] *= al0; oacc[nt][1] *= al0;
            oacc[nt][2] *= al1; oacc[nt][3] *= al1;
        }

        // ---- P accumulator -> A fragments ----
        uint32_t pa[4][4];
        #pragma unroll
        for (int ks = 0; ks < 4; ks++) {
            pa[ks][0] = f2h2(sacc[2 * ks][0],     sacc[2 * ks][1]);
            pa[ks][1] = f2h2(sacc[2 * ks][2],     sacc[2 * ks][3]);
            pa[ks][2] = f2h2(sacc[2 * ks + 1][0], sacc[2 * ks + 1][1]);
            pa[ks][3] = f2h2(sacc[2 * ks + 1][2], sacc[2 * ks + 1][3]);
        }

        // ---- O += P @ V ----
        #pragma unroll
        for (int dtp = 0; dtp < 4; dtp++) {
            #pragma unroll
            for (int ks = 0; ks < 4; ks++) {
                int row = dtp * 16 + rb;
                uint32_t off = (uint32_t)row * 128u +
                               (((uint32_t)(ks * 2 + cb) ^ (uint32_t)(row & 7)) << 4);
                uint32_t v0, v1, v2, v3;
                ldsm4(v0, v1, v2, v3, VTu + off);
                mma16816(oacc[2 * dtp],     pa[ks][0], pa[ks][1], pa[ks][2], pa[ks][3], v0, v1);
                mma16816(oacc[2 * dtp + 1], pa[ks][0], pa[ks][1], pa[ks][2], pa[ks][3], v2, v3);
            }
        }
    }

    // ---- normalize + store ----
    float inv0 = (lsum0 > 0.f) ? (1.f / lsum0) : 0.f;
    float inv1 = (lsum1 > 0.f) ? (1.f / lsum1) : 0.f;
    float* op0 = Og + ((size_t)bh * SLEN + r0g) * HD;
    float* op1 = op0 + 8 * HD;
    #pragma unroll
    for (int nt = 0; nt < 8; nt++) {
        int c = nt * 8 + (lane & 3) * 2;
        float2 o0 = {oacc[nt][0] * inv0, oacc[nt][1] * inv0};
        float2 o1 = {oacc[nt][2] * inv1, oacc[nt][3] * inv1};
        *reinterpret_cast<float2*>(op0 + c) = o0;
        *reinterpret_cast<float2*>(op1 + c) = o1;
    }
}

extern "C" void kernel_launch(void* const* d_in, const int* in_sizes, int n_in,
                              void* d_out, int out_size) {
    const float* Q    = (const float*)d_in[0];
    const float* K    = (const float*)d_in[1];
    const float* V    = (const float*)d_in[2];
    const int*   mask = (const int*)d_in[3];
    float* O = (float*)d_out;

    static bool attr_set = false;
    if (!attr_set) {
        cudaFuncSetAttribute(fa_hmma_kernel, cudaFuncAttributeMaxDynamicSharedMemorySize,
                             SMEM_TOTAL);
        attr_set = true;
    }

    pack_mask_kernel<<<1024, 256>>>(mask);
    dim3 grid(SLEN / TQ, NH, 4);
    fa_hmma_kernel<<<grid, 256, SMEM_TOTAL>>>(Q, K, V, O);
}